// round 1
// baseline (speedup 1.0000x reference)
#include <cuda_runtime.h>

#define BB 32
#define SS 1024
#define DD 512
#define DD4 (DD/4)
#define MAXL 8192   // durations in [1,8], S=1024 -> mel_len <= 8192

// Scratch (no device allocation allowed)
__device__ int g_csum[BB * SS];
__device__ int g_idx[BB * MAXL];   // global source row b*S+idx, or -1 for padding

// ---------------------------------------------------------------------------
// K1: per-batch inclusive scan of durations (Hillis-Steele in shared memory).
// Also writes mel_len (as float) into the output tail if present.
// ---------------------------------------------------------------------------
__global__ void lr_cumsum_kernel(const int* __restrict__ dur,
                                 float* __restrict__ mel_len_out,
                                 int write_tail)
{
    __shared__ int s[SS];
    const int b = blockIdx.x;
    const int tid = threadIdx.x;
    s[tid] = dur[b * SS + tid];
    #pragma unroll
    for (int off = 1; off < SS; off <<= 1) {
        __syncthreads();
        int v = (tid >= off) ? s[tid - off] : 0;
        __syncthreads();
        s[tid] += v;
    }
    g_csum[b * SS + tid] = s[tid];
    if (write_tail && tid == SS - 1) {
        mel_len_out[b] = (float)s[tid];
    }
}

// ---------------------------------------------------------------------------
// K2: per output time-step, binary-search the cumsum row for the source token
// (first i with csum[i] > t), store global row index; write mel_mask floats.
// ---------------------------------------------------------------------------
__global__ void lr_idx_kernel(int max_len,
                              float* __restrict__ mask_out,
                              int write_mask)
{
    const int r = blockIdx.x * blockDim.x + threadIdx.x;
    const int total = BB * max_len;
    if (r >= total) return;
    const int b = r / max_len;
    const int t = r - b * max_len;
    const int* __restrict__ csum = g_csum + b * SS;
    const int mel = csum[SS - 1];
    if (t >= mel) {
        g_idx[r] = -1;
        if (write_mask) mask_out[r] = 1.0f;
        return;
    }
    // first index lo in [0, S-1] with csum[lo] > t (guaranteed since csum[S-1]=mel>t)
    int lo = 0, hi = SS - 1;
    #pragma unroll
    for (int it = 0; it < 10; ++it) {  // ceil(log2(1024)) = 10
        int mid = (lo + hi) >> 1;
        if (lo < hi) {
            if (csum[mid] > t) hi = mid; else lo = mid + 1;
        }
    }
    g_idx[r] = b * SS + lo;
    if (write_mask) mask_out[r] = 0.0f;
}

// ---------------------------------------------------------------------------
// K3: streaming gather-expand. One thread per output float4.
// 128 consecutive threads share one g_idx entry (broadcast L1 hit).
// ---------------------------------------------------------------------------
__global__ void lr_expand_kernel(const float4* __restrict__ x4,
                                 float4* __restrict__ out4,
                                 long total4)
{
    const long i = (long)blockIdx.x * blockDim.x + threadIdx.x;
    if (i >= total4) return;
    const long r  = i >> 7;          // output row (b * max_len + t)
    const int  d4 = (int)(i & 127);  // float4 index within the 512-dim row
    const int  src = g_idx[r];
    float4 v;
    if (src < 0) {
        v = make_float4(0.f, 0.f, 0.f, 0.f);
    } else {
        v = __ldg(&x4[(long)src * DD4 + d4]);
    }
    out4[i] = v;
}

// ---------------------------------------------------------------------------
extern "C" void kernel_launch(void* const* d_in, const int* in_sizes, int n_in,
                              void* d_out, int out_size)
{
    const float* x   = (const float*)d_in[0];
    const int*   dur = (const int*)d_in[1];
    float*       out = (float*)d_out;

    // Recover max_len from out_size.
    // Layout A (tuple of 3): out_size = B*L*D + B + B*L  ->  L = (out_size-B)/(B*(D+1))
    // Layout B (expanded only): out_size = B*L*D         ->  L = out_size/(B*D)
    long L;
    int has_tail;
    long os = (long)out_size;
    if ((os - BB) > 0 && ((os - BB) % ((long)BB * (DD + 1))) == 0) {
        L = (os - BB) / ((long)BB * (DD + 1));
        has_tail = 1;
    } else {
        L = os / ((long)BB * DD);
        has_tail = 0;
    }
    if (L <= 0 || L > MAXL) return;

    const int max_len = (int)L;
    float* mel_len_out = out + (long)BB * max_len * DD;         // B floats
    float* mask_out    = mel_len_out + BB;                      // B*L floats

    // K1: cumsum (+ mel_len tail)
    lr_cumsum_kernel<<<BB, SS>>>(dur, mel_len_out, has_tail);

    // K2: source indices (+ mask tail)
    {
        int total = BB * max_len;
        int threads = 256;
        int blocks = (total + threads - 1) / threads;
        lr_idx_kernel<<<blocks, threads>>>(max_len, mask_out, has_tail);
    }

    // K3: expand
    {
        long total4 = (long)BB * max_len * DD4;
        int threads = 256;
        long blocks = (total4 + threads - 1) / threads;
        lr_expand_kernel<<<(unsigned)blocks, threads>>>(
            (const float4*)x, (float4*)out, total4);
    }
}

// round 2
// speedup vs baseline: 1.6000x; 1.6000x over previous
#include <cuda_runtime.h>

#define BB 32
#define SS 1024
#define DD 512
#define DD4 (DD/4)
#define MAXL 8192   // durations in [1,8], S=1024 -> mel_len <= 8192

// Scratch (no device allocation allowed)
// g_idx[r] = global source row b*S+idx, or -1 for padding
__device__ int g_idx[BB * MAXL];

// ---------------------------------------------------------------------------
// K1 (fused scan + index build): one 1024-thread block per batch.
//  - warp-shuffle inclusive scan of durations (2 barriers total)
//  - csum kept in smem; per-t binary search runs against smem (LDS, not L2)
//  - writes g_idx, mel_len (fp32) and mel_mask (fp32) tails
// ---------------------------------------------------------------------------
__global__ __launch_bounds__(SS)
void lr_scan_idx_kernel(const int* __restrict__ dur,
                        float* __restrict__ mel_len_out,
                        float* __restrict__ mask_out,
                        int max_len, int has_tail)
{
    __shared__ int s[SS];
    __shared__ int warp_sums[32];

    const int b    = blockIdx.x;
    const int tid  = threadIdx.x;
    const int lane = tid & 31;
    const int wid  = tid >> 5;

    int v = dur[b * SS + tid];

    // intra-warp inclusive scan
    #pragma unroll
    for (int off = 1; off < 32; off <<= 1) {
        int n = __shfl_up_sync(0xffffffff, v, off);
        if (lane >= off) v += n;
    }
    if (lane == 31) warp_sums[wid] = v;
    __syncthreads();

    // scan of 32 warp sums by warp 0
    if (wid == 0) {
        int w = warp_sums[lane];
        #pragma unroll
        for (int off = 1; off < 32; off <<= 1) {
            int n = __shfl_up_sync(0xffffffff, w, off);
            if (lane >= off) w += n;
        }
        warp_sums[lane] = w;
    }
    __syncthreads();

    s[tid] = v + ((wid > 0) ? warp_sums[wid - 1] : 0);
    __syncthreads();

    const int mel = s[SS - 1];
    if (has_tail && tid == 0) mel_len_out[b] = (float)mel;

    // per output time-step: binary search in smem csum
    for (int t = tid; t < max_len; t += SS) {
        const int r = b * max_len + t;
        if (t >= mel) {
            g_idx[r] = -1;
            if (has_tail) mask_out[r] = 1.0f;
        } else {
            int lo = 0, hi = SS - 1;   // first i with s[i] > t
            #pragma unroll
            for (int it = 0; it < 10; ++it) {
                if (lo < hi) {
                    int mid = (lo + hi) >> 1;
                    if (s[mid] > t) hi = mid; else lo = mid + 1;
                }
            }
            g_idx[r] = b * SS + lo;
            if (has_tail) mask_out[r] = 0.0f;
        }
    }
}

// ---------------------------------------------------------------------------
// K3: streaming gather-expand. ONE WARP PER OUTPUT ROW.
// Lane l handles float4s l, l+32, l+64, l+96 of the 128-float4 row:
//  - g_idx loaded once per warp (uniform broadcast)
//  - 4 independent LDG.128 + 4 STG.128 per thread -> MLP=4
//  - __stcs streaming stores: keep x resident in L2 (output is write-once)
// ---------------------------------------------------------------------------
__global__ __launch_bounds__(256)
void lr_expand_kernel(const float4* __restrict__ x4,
                      float4* __restrict__ out4,
                      int total_rows)
{
    const int warp_global = (blockIdx.x * blockDim.x + threadIdx.x) >> 5;
    const int lane = threadIdx.x & 31;
    if (warp_global >= total_rows) return;

    const int  src      = g_idx[warp_global];
    const long out_base = (long)warp_global * DD4 + lane;

    if (src < 0) {
        const float4 z = make_float4(0.f, 0.f, 0.f, 0.f);
        #pragma unroll
        for (int j = 0; j < 4; ++j)
            __stcs(&out4[out_base + 32 * j], z);
    } else {
        const long in_base = (long)src * DD4 + lane;
        float4 v0 = __ldg(&x4[in_base]);
        float4 v1 = __ldg(&x4[in_base + 32]);
        float4 v2 = __ldg(&x4[in_base + 64]);
        float4 v3 = __ldg(&x4[in_base + 96]);
        __stcs(&out4[out_base],      v0);
        __stcs(&out4[out_base + 32], v1);
        __stcs(&out4[out_base + 64], v2);
        __stcs(&out4[out_base + 96], v3);
    }
}

// ---------------------------------------------------------------------------
extern "C" void kernel_launch(void* const* d_in, const int* in_sizes, int n_in,
                              void* d_out, int out_size)
{
    const float* x   = (const float*)d_in[0];
    const int*   dur = (const int*)d_in[1];
    float*       out = (float*)d_out;

    // Recover max_len from out_size.
    // Layout A (tuple of 3): out_size = B*L*D + B + B*L  ->  L = (out_size-B)/(B*(D+1))
    // Layout B (expanded only): out_size = B*L*D         ->  L = out_size/(B*D)
    long L;
    int has_tail;
    long os = (long)out_size;
    if ((os - BB) > 0 && ((os - BB) % ((long)BB * (DD + 1))) == 0) {
        L = (os - BB) / ((long)BB * (DD + 1));
        has_tail = 1;
    } else {
        L = os / ((long)BB * DD);
        has_tail = 0;
    }
    if (L <= 0 || L > MAXL) return;

    const int max_len = (int)L;
    float* mel_len_out = out + (long)BB * max_len * DD;   // B floats
    float* mask_out    = mel_len_out + BB;                // B*L floats

    // Fused scan + index build (one block per batch)
    lr_scan_idx_kernel<<<BB, SS>>>(dur, mel_len_out, mask_out, max_len, has_tail);

    // Expand: one warp per output row
    {
        const int total_rows = BB * max_len;
        const int warps_per_block = 256 / 32;
        const int blocks = (total_rows + warps_per_block - 1) / warps_per_block;
        lr_expand_kernel<<<blocks, 256>>>((const float4*)x, (float4*)out, total_rows);
    }
}